// round 3
// baseline (speedup 1.0000x reference)
#include <cuda_runtime.h>

#define NN 100000
#define NE 1600000
#define FD 64
#define NB_SCAN 98   // ceil(NN/1024)

// ---------------- device scratch (allocation-free contract) ----------------
__device__ int   g_flag32;           // 1 => edge_index stored as int32
__device__ int   g_edges[2 * NE];    // normalized int32 edge list
__device__ int   g_cnt[NN];          // histogram, then scatter write-cursors
__device__ int   g_rowptr[NN + 1];
__device__ int   g_part[128];
__device__ int   g_srcs[NE];         // src ids bucketed by dst (CSR payload)
__device__ float g_agg[(size_t)NN * FD];
__device__ float g_h1 [(size_t)NN * FD];
__device__ float g_h2 [(size_t)NN * FD];

// ---------------- edge dtype detection + normalization ----------------
__global__ void k_detect(const void* __restrict__ ei_raw) {
    // Interpret first 4096 entries as int64. If the buffer is really int32,
    // nearly every fused pair lands outside [0, NN) -> set int32 flag.
    if (blockIdx.x == 0 && threadIdx.x == 0) g_flag32 = 0;
    __syncthreads();
    const long long* e64 = (const long long*)ei_raw;
    int i = threadIdx.x;
    long long v = e64[i & 4095];
    if (v < 0 || v >= NN) atomicOr(&g_flag32, 1);
}

__global__ void k_convert(const void* __restrict__ ei_raw) {
    int i = blockIdx.x * blockDim.x + threadIdx.x;
    if (i >= 2 * NE) return;
    if (g_flag32) g_edges[i] = ((const int*)ei_raw)[i];
    else          g_edges[i] = (int)((const long long*)ei_raw)[i];
}

// ---------------- CSR build ----------------
__global__ void k_zero() {
    int i = blockIdx.x * blockDim.x + threadIdx.x;
    if (i < NN) g_cnt[i] = 0;
}

__global__ void k_hist() {
    int e = blockIdx.x * blockDim.x + threadIdx.x;
    if (e < NE) atomicAdd(&g_cnt[g_edges[NE + e]], 1);
}

__global__ void k_scan1() {  // per-1024-block exclusive scan of g_cnt -> g_rowptr
    __shared__ int s_w[32];
    int tid  = threadIdx.x;
    int idx  = blockIdx.x * 1024 + tid;
    int lane = tid & 31, wid = tid >> 5;
    int v = (idx < NN) ? g_cnt[idx] : 0;
    int inc = v;
#pragma unroll
    for (int o = 1; o < 32; o <<= 1) {
        int t = __shfl_up_sync(0xffffffffu, inc, o);
        if (lane >= o) inc += t;
    }
    if (lane == 31) s_w[wid] = inc;
    __syncthreads();
    if (wid == 0) {
        int w = s_w[lane];
#pragma unroll
        for (int o = 1; o < 32; o <<= 1) {
            int t = __shfl_up_sync(0xffffffffu, w, o);
            if (lane >= o) w += t;
        }
        s_w[lane] = w;
    }
    __syncthreads();
    int boff = wid ? s_w[wid - 1] : 0;
    if (idx < NN) g_rowptr[idx] = inc - v + boff;  // exclusive within block
    if (tid == 0) g_part[blockIdx.x] = s_w[31];    // block total
}

__global__ void k_scan2() {  // exclusive scan of the 98 block partials
    __shared__ int s[128];
    int tid = threadIdx.x;
    s[tid] = (tid < NB_SCAN) ? g_part[tid] : 0;
    __syncthreads();
    if (tid == 0) {
        int run = 0;
        for (int i = 0; i < NB_SCAN; i++) { int t = s[i]; s[i] = run; run += t; }
    }
    __syncthreads();
    if (tid < NB_SCAN) g_part[tid] = s[tid];
}

__global__ void k_scan3() {  // add block offsets; duplicate rowptr into cursors
    int i = blockIdx.x * blockDim.x + threadIdx.x;
    if (i < NN) {
        int v = g_rowptr[i] + g_part[i >> 10];
        g_rowptr[i] = v;
        g_cnt[i]    = v;
    } else if (i == NN) {
        g_rowptr[NN] = NE;
    }
}

__global__ void k_scatter() {
    int e = blockIdx.x * blockDim.x + threadIdx.x;
    if (e < NE) {
        int src = g_edges[e];
        int dst = g_edges[NE + e];
        int pos = atomicAdd(&g_cnt[dst], 1);
        g_srcs[pos] = src;
    }
}

// ---------------- mean aggregation: one warp per dst node ----------------
__global__ void k_agg(const float* __restrict__ feat, float* __restrict__ agg) {
    int warp = (blockIdx.x * blockDim.x + threadIdx.x) >> 5;
    int lane = threadIdx.x & 31;
    if (warp >= NN) return;
    int beg = g_rowptr[warp], end = g_rowptr[warp + 1];
    float2 a = make_float2(0.f, 0.f);
    for (int e = beg; e < end; e++) {
        int s = g_srcs[e];
        float2 v = *(const float2*)(feat + (size_t)s * FD + 2 * lane);
        a.x += v.x; a.y += v.y;
    }
    float inv = (end > beg) ? 1.f / (float)(end - beg) : 0.f;
    a.x *= inv; a.y *= inv;
    *(float2*)(agg + (size_t)warp * FD + 2 * lane) = a;
}

// ---------------- fused SAGE GEMM: out = relu(agg@Wa + x@Wr + b) ----------------
// block: 64 rows x 64 cols, 256 threads, 4x4 microtile per thread
__global__ void k_sage_gemm(const float* __restrict__ A, const float* __restrict__ X,
                            const float* __restrict__ Wa, const float* __restrict__ Wr,
                            const float* __restrict__ b, float* __restrict__ out) {
    extern __shared__ float sm[];
    float* sA  = sm;                 // 64 x 68 (padded)
    float* sX  = sA + 64 * 68;
    float* sWa = sX + 64 * 68;       // 64 x 64 row-major
    float* sWr = sWa + 64 * 64;
    float* sb  = sWr + 64 * 64;      // 64
    int tid  = threadIdx.x;
    int base = blockIdx.x * 64;

    {
        const float4* wa4 = (const float4*)Wa;
        const float4* wr4 = (const float4*)Wr;
        float4* da4 = (float4*)sWa;
        float4* dr4 = (float4*)sWr;
        for (int i = tid; i < 1024; i += 256) { da4[i] = wa4[i]; dr4[i] = wr4[i]; }
        if (tid < 64) sb[tid] = b[tid];
    }
    for (int i = tid; i < 4096; i += 256) {
        int r = i >> 6, k = i & 63;
        int row = base + r;
        float va = 0.f, vx = 0.f;
        if (row < NN) { va = A[(size_t)row * FD + k]; vx = X[(size_t)row * FD + k]; }
        sA[r * 68 + k] = va;
        sX[r * 68 + k] = vx;
    }
    __syncthreads();

    int tx = tid & 15, ty = tid >> 4;
    int r0 = ty * 4, c0 = tx * 4;
    float acc[4][4];
#pragma unroll
    for (int i = 0; i < 4; i++)
#pragma unroll
        for (int j = 0; j < 4; j++) acc[i][j] = 0.f;

#pragma unroll 8
    for (int k = 0; k < 64; k++) {
        float av[4], xv[4];
#pragma unroll
        for (int i = 0; i < 4; i++) {
            av[i] = sA[(r0 + i) * 68 + k];
            xv[i] = sX[(r0 + i) * 68 + k];
        }
        float4 wa = *(const float4*)(sWa + k * 64 + c0);
        float4 wr = *(const float4*)(sWr + k * 64 + c0);
        float wav[4] = {wa.x, wa.y, wa.z, wa.w};
        float wrv[4] = {wr.x, wr.y, wr.z, wr.w};
#pragma unroll
        for (int i = 0; i < 4; i++)
#pragma unroll
            for (int j = 0; j < 4; j++)
                acc[i][j] += av[i] * wav[j] + xv[i] * wrv[j];
    }

#pragma unroll
    for (int i = 0; i < 4; i++) {
        int row = base + r0 + i;
        if (row < NN) {
            float4 o;
            o.x = fmaxf(acc[i][0] + sb[c0 + 0], 0.f);
            o.y = fmaxf(acc[i][1] + sb[c0 + 1], 0.f);
            o.z = fmaxf(acc[i][2] + sb[c0 + 2], 0.f);
            o.w = fmaxf(acc[i][3] + sb[c0 + 3], 0.f);
            *(float4*)(out + (size_t)row * FD + c0) = o;
        }
    }
}

// ---------------- final head: out = h2 @ W_lin + b_lin  (warp per node) ----------------
__global__ void k_final(const float* __restrict__ h, const float* __restrict__ Wl,
                        const float* __restrict__ bl, float* __restrict__ out) {
    int warp = (blockIdx.x * blockDim.x + threadIdx.x) >> 5;
    int lane = threadIdx.x & 31;
    if (warp >= NN) return;
    float2 hv = *(const float2*)(h + (size_t)warp * FD + 2 * lane);
    float4 w  = *(const float4*)(Wl + 4 * lane);  // W[2l][0..1], W[2l+1][0..1]
    float a0 = hv.x * w.x + hv.y * w.z;
    float a1 = hv.x * w.y + hv.y * w.w;
#pragma unroll
    for (int o = 16; o; o >>= 1) {
        a0 += __shfl_xor_sync(0xffffffffu, a0, o);
        a1 += __shfl_xor_sync(0xffffffffu, a1, o);
    }
    if (lane == 0) {
        out[(size_t)warp * 2 + 0] = a0 + bl[0];
        out[(size_t)warp * 2 + 1] = a1 + bl[1];
    }
}

// ---------------- launch ----------------
extern "C" void kernel_launch(void* const* d_in, const int* in_sizes, int n_in,
                              void* d_out, int out_size) {
    const float* x   = (const float*)d_in[0];
    const void*  ei  = d_in[1];
    const float* W1a = (const float*)d_in[2];
    const float* W1r = (const float*)d_in[3];
    const float* b1  = (const float*)d_in[4];
    const float* W2a = (const float*)d_in[5];
    const float* W2r = (const float*)d_in[6];
    const float* b2  = (const float*)d_in[7];
    const float* Wl  = (const float*)d_in[8];
    const float* bl  = (const float*)d_in[9];
    float*       out = (float*)d_out;

    (void)in_sizes; (void)n_in; (void)out_size;

    cudaFuncSetAttribute(k_sage_gemm, cudaFuncAttributeMaxDynamicSharedMemorySize, 69632);

    float *agg, *h1, *h2;
    cudaGetSymbolAddress((void**)&agg, g_agg);
    cudaGetSymbolAddress((void**)&h1,  g_h1);
    cudaGetSymbolAddress((void**)&h2,  g_h2);

    const size_t gemm_smem = (2 * 64 * 68 + 2 * 64 * 64 + 64) * sizeof(float);

    // ---- edge dtype normalize + CSR build ----
    k_detect <<<1, 1024>>>(ei);
    k_convert<<<(2 * NE + 255) / 256, 256>>>(ei);
    k_zero   <<<(NN + 255) / 256, 256>>>();
    k_hist   <<<NE / 256, 256>>>();
    k_scan1  <<<NB_SCAN, 1024>>>();
    k_scan2  <<<1, 128>>>();
    k_scan3  <<<(NN + 1 + 255) / 256, 256>>>();
    k_scatter<<<NE / 256, 256>>>();

    // ---- layer 1 ----
    k_agg      <<<12500, 256>>>(x, agg);
    k_sage_gemm<<<(NN + 63) / 64, 256, gemm_smem>>>(agg, x, W1a, W1r, b1, h1);

    // ---- layer 2 ----
    k_agg      <<<12500, 256>>>(h1, agg);
    k_sage_gemm<<<(NN + 63) / 64, 256, gemm_smem>>>(agg, h1, W2a, W2r, b2, h2);

    // ---- head ----
    k_final<<<12500, 256>>>(h2, Wl, bl, out);
}